// round 3
// baseline (speedup 1.0000x reference)
#include <cuda_runtime.h>
#include <stdint.h>

// FieldAwareFM: B=16384 samples, F=10 fields, D=8.
// out[b] = b_lin + sum_f w[idx_f] + sum_{f<g} <emb[f][idx_g], emb[g][idx_f]>
//
// Warp-per-sample, wavefront-coalesced gathers with BATCHED issue:
//   slot p = 8*t + (lane>>2); role = (lane>>1)&1; half = lane&1.
//   role 0 loads emb[f][idx_g] half, role 1 loads emb[g][idx_f] half;
//   adjacent lanes (half 0/1) share a 128B line -> 1 L1 wavefront per 32B row.
//   ALL 6 gathers are issued back-to-back into v[6] (MLP=6), then consumed.
//   Dot: shfl_xor by 2 swaps roles; each pair dot computed twice -> *0.5.

#define BATCH      16384
#define NUM_FIELDS 10
#define FACTOR_DIM 8
#define INPUT_DIM  188610
#define NUM_PAIRS  45
#define NUM_ROUNDS 6

__constant__ int c_offsets[NUM_FIELDS] = {
    0, 100000, 150000, 170000, 180000, 185000, 187000, 188000, 188500, 188600
};

// c_tbl[2p + role]: low nibble = embedding-table index, high nibble = index-field
// role 0: (g<<4)|f   role 1: (f<<4)|g
__constant__ unsigned char c_tbl[2 * 48] = {
    0x10,0x01, 0x20,0x02, 0x30,0x03, 0x40,0x04, 0x50,0x05, 0x60,0x06, 0x70,0x07, 0x80,0x08,
    0x90,0x09, 0x21,0x12, 0x31,0x13, 0x41,0x14, 0x51,0x15, 0x61,0x16, 0x71,0x17, 0x81,0x18,
    0x91,0x19, 0x32,0x23, 0x42,0x24, 0x52,0x25, 0x62,0x26, 0x72,0x27, 0x82,0x28, 0x92,0x29,
    0x43,0x34, 0x53,0x35, 0x63,0x36, 0x73,0x37, 0x83,0x38, 0x93,0x39, 0x54,0x45, 0x64,0x46,
    0x74,0x47, 0x84,0x48, 0x94,0x49, 0x65,0x56, 0x75,0x57, 0x85,0x58, 0x95,0x59, 0x76,0x67,
    0x86,0x68, 0x96,0x69, 0x87,0x78, 0x97,0x79, 0x98,0x89, 0x00,0x00, 0x00,0x00, 0x00,0x00
};

__global__ __launch_bounds__(128)
void ffm_kernel(const int* __restrict__ x,
                const float* __restrict__ w,
                const float* __restrict__ b_lin,
                const float* __restrict__ emb,
                float* __restrict__ out)
{
    const int warp_in_block = threadIdx.x >> 5;
    const int lane          = threadIdx.x & 31;
    const int b             = blockIdx.x * (blockDim.x >> 5) + warp_in_block;
    const unsigned full     = 0xffffffffu;

    const float bias = __ldg(&b_lin[0]);   // hoisted, L1/L2-broadcast

    // lanes 0..9: sample's global indices (coalesced 40B)
    int my_idx = 0;
    if (lane < NUM_FIELDS) {
        my_idx = x[b * NUM_FIELDS + lane] + c_offsets[lane];
    }

    // linear gather (independent of everything below, issues early)
    float lin = 0.0f;
    if (lane < NUM_FIELDS) {
        lin = __ldg(&w[my_idx]);
    }

    // ---- Phase A: compute all 6 gather addresses and issue all loads ----
    const float4* addr[NUM_ROUNDS];
    bool valid[NUM_ROUNDS];
#pragma unroll
    for (int t = 0; t < NUM_ROUNDS; t++) {
        const int e   = (int)c_tbl[(((t * 8 + (lane >> 2)) << 1) | ((lane >> 1) & 1))];
        const int row = e & 15;
        const int col = e >> 4;
        const int idx = __shfl_sync(full, my_idx, col);
        valid[t] = (t * 8 + (lane >> 2)) < NUM_PAIRS;
        addr[t]  = (const float4*)(emb + ((size_t)row * INPUT_DIM + (size_t)idx) * FACTOR_DIM)
                   + (lane & 1);
    }

    float4 v[NUM_ROUNDS];
#pragma unroll
    for (int t = 0; t < NUM_ROUNDS; t++) {
        v[t] = valid[t] ? __ldg(addr[t]) : make_float4(0.f, 0.f, 0.f, 0.f);
    }

    // ---- Phase B: partner exchange + dot accumulate ----
    float ffm = 0.0f;
#pragma unroll
    for (int t = 0; t < NUM_ROUNDS; t++) {
        float ux = __shfl_xor_sync(full, v[t].x, 2);
        float uy = __shfl_xor_sync(full, v[t].y, 2);
        float uz = __shfl_xor_sync(full, v[t].z, 2);
        float uw = __shfl_xor_sync(full, v[t].w, 2);
        ffm += v[t].x * ux + v[t].y * uy + v[t].z * uz + v[t].w * uw;
    }

    float acc = 0.5f * ffm + lin;

#pragma unroll
    for (int off = 16; off > 0; off >>= 1) {
        acc += __shfl_xor_sync(full, acc, off);
    }

    if (lane == 0) {
        out[b] = acc + bias;
    }
}

extern "C" void kernel_launch(void* const* d_in, const int* in_sizes, int n_in,
                              void* d_out, int out_size)
{
    (void)in_sizes; (void)n_in; (void)out_size;
    const int*   x     = (const int*)d_in[0];
    const float* w     = (const float*)d_in[1];
    const float* b_lin = (const float*)d_in[2];
    const float* emb   = (const float*)d_in[3];
    float*       out   = (float*)d_out;

    const int warps_per_block = 4;              // 128 threads
    const int blocks = BATCH / warps_per_block; // 4096
    ffm_kernel<<<blocks, warps_per_block * 32>>>(x, w, b_lin, emb, out);
}

// round 4
// speedup vs baseline: 1.0887x; 1.0887x over previous
#include <cuda_runtime.h>
#include <stdint.h>

// FieldAwareFM: B=16384, F=10, D=8.
// out[b] = b_lin + sum_f w[idx_f] + sum_{f<g} <emb[f][idx_g], emb[g][idx_f]>
//
// Gather path: cp.async.cg (LDGSTS, 16B, L1-bypass) into per-warp smem staging,
// escaping the per-SM L1tex LDG wavefront-queue cap that pinned rounds 1-3 at
// ~19us. Lane (4q+2r+h) stages 16B half h of role r's row for pair slot
// p = 8t+q. Compute: read own 16B back (conflict-free LDS.128), shfl_xor(2)
// exchanges roles, each pair dot counted twice -> *0.5.

#define BATCH      16384
#define NUM_FIELDS 10
#define FACTOR_DIM 8
#define INPUT_DIM  188610
#define NUM_PAIRS  45
#define NUM_ROUNDS 6
#define WARPS_PER_BLOCK 8
#define SLOT_BYTES 64                       // 2 roles x 32B row
#define WARP_STAGE_BYTES (48 * SLOT_BYTES)  // 3072B per warp

__constant__ int c_offsets[NUM_FIELDS] = {
    0, 100000, 150000, 170000, 180000, 185000, 187000, 188000, 188500, 188600
};

// c_tbl[2p + role]: low nibble = embedding-table index, high nibble = index-field
// role 0: (g<<4)|f   role 1: (f<<4)|g    (pads p=45..47 -> 0x00: safe addr)
__constant__ unsigned char c_tbl[2 * 48] = {
    0x10,0x01, 0x20,0x02, 0x30,0x03, 0x40,0x04, 0x50,0x05, 0x60,0x06, 0x70,0x07, 0x80,0x08,
    0x90,0x09, 0x21,0x12, 0x31,0x13, 0x41,0x14, 0x51,0x15, 0x61,0x16, 0x71,0x17, 0x81,0x18,
    0x91,0x19, 0x32,0x23, 0x42,0x24, 0x52,0x25, 0x62,0x26, 0x72,0x27, 0x82,0x28, 0x92,0x29,
    0x43,0x34, 0x53,0x35, 0x63,0x36, 0x73,0x37, 0x83,0x38, 0x93,0x39, 0x54,0x45, 0x64,0x46,
    0x74,0x47, 0x84,0x48, 0x94,0x49, 0x65,0x56, 0x75,0x57, 0x85,0x58, 0x95,0x59, 0x76,0x67,
    0x86,0x68, 0x96,0x69, 0x87,0x78, 0x97,0x79, 0x98,0x89, 0x00,0x00, 0x00,0x00, 0x00,0x00
};

__device__ __forceinline__ uint32_t smem_u32(const void* p) {
    uint32_t a;
    asm("{ .reg .u64 t; cvta.to.shared.u64 t, %1; cvt.u32.u64 %0, t; }" : "=r"(a) : "l"(p));
    return a;
}

__global__ __launch_bounds__(WARPS_PER_BLOCK * 32)
void ffm_kernel(const int* __restrict__ x,
                const float* __restrict__ w,
                const float* __restrict__ b_lin,
                const float* __restrict__ emb,
                float* __restrict__ out)
{
    __shared__ __align__(16) char stage[WARPS_PER_BLOCK * WARP_STAGE_BYTES];

    const int warp_in_block = threadIdx.x >> 5;
    const int lane          = threadIdx.x & 31;
    const int b             = blockIdx.x * WARPS_PER_BLOCK + warp_in_block;
    const unsigned full     = 0xffffffffu;

    const float bias = __ldg(&b_lin[0]);

    // lanes 0..9: this sample's global indices (coalesced 40B)
    int my_idx = 0;
    if (lane < NUM_FIELDS) {
        my_idx = x[b * NUM_FIELDS + lane] + c_offsets[lane];
    }
    float lin = 0.0f;
    if (lane < NUM_FIELDS) {
        lin = __ldg(&w[my_idx]);
    }

    // per-lane staging address: slot q of round t, role r, half h
    const int q = lane >> 2;          // pair slot within round
    const uint32_t my_stage = smem_u32(stage)
        + (uint32_t)warp_in_block * WARP_STAGE_BYTES
        + (uint32_t)(lane << 4);      // q*64 + r*32 + h*16 == lane*16

    // ---- Phase A: issue all 6 cp.async gathers (no L1tex LDG queue) ----
#pragma unroll
    for (int t = 0; t < NUM_ROUNDS; t++) {
        const int e   = (int)c_tbl[(((t * 8 + q) << 1) | ((lane >> 1) & 1))];
        const int row = e & 15;
        const int col = e >> 4;
        const int idx = __shfl_sync(full, my_idx, col);
        const float* gptr = emb + ((size_t)row * INPUT_DIM + (size_t)idx) * FACTOR_DIM
                                + ((lane & 1) << 2);
        const uint32_t saddr = my_stage + (uint32_t)(t * 512); // 8 slots * 64B per round
        asm volatile("cp.async.cg.shared.global [%0], [%1], 16;\n"
                     :: "r"(saddr), "l"(gptr) : "memory");
    }
    asm volatile("cp.async.commit_group;\n" ::: "memory");
    asm volatile("cp.async.wait_group 0;\n" ::: "memory");
    __syncwarp(full);

    // ---- Phase B: read back own 16B chunks, exchange roles, accumulate ----
    float ffm = 0.0f;
#pragma unroll
    for (int t = 0; t < NUM_ROUNDS; t++) {
        float4 v = *(const float4*)(stage + (my_stage - smem_u32(stage)) + t * 512);
        float ux = __shfl_xor_sync(full, v.x, 2);
        float uy = __shfl_xor_sync(full, v.y, 2);
        float uz = __shfl_xor_sync(full, v.z, 2);
        float uw = __shfl_xor_sync(full, v.w, 2);
        float d  = v.x * ux + v.y * uy + v.z * uz + v.w * uw;
        if ((t * 8 + q) < NUM_PAIRS) ffm += d;
    }

    float acc = 0.5f * ffm + lin;

#pragma unroll
    for (int off = 16; off > 0; off >>= 1) {
        acc += __shfl_xor_sync(full, acc, off);
    }

    if (lane == 0) {
        out[b] = acc + bias;
    }
}

extern "C" void kernel_launch(void* const* d_in, const int* in_sizes, int n_in,
                              void* d_out, int out_size)
{
    (void)in_sizes; (void)n_in; (void)out_size;
    const int*   x     = (const int*)d_in[0];
    const float* w     = (const float*)d_in[1];
    const float* b_lin = (const float*)d_in[2];
    const float* emb   = (const float*)d_in[3];
    float*       out   = (float*)d_out;

    const int blocks = BATCH / WARPS_PER_BLOCK;  // 2048
    ffm_kernel<<<blocks, WARPS_PER_BLOCK * 32>>>(x, w, b_lin, emb, out);
}